// round 1
// baseline (speedup 1.0000x reference)
#include <cuda_runtime.h>

// QuantumSelfAttention: reference computes softmax(z, axis=-1).mean(axis=-1).
// softmax rows sum to 1, so the mean over that same axis is identically 1/4
// for every sample, independent of the circuit. Output = 0.25 everywhere.
//
// out_size = seq_len * batch * 1 = 2048 * 256 = 524288 floats (2 MiB).
// Write-only fill with float4 stores; grid-stride for generality.

__global__ void qsa_fill_kernel(float4* __restrict__ out4, int n4) {
    const float4 v = make_float4(0.25f, 0.25f, 0.25f, 0.25f);
    int idx = blockIdx.x * blockDim.x + threadIdx.x;
    int stride = gridDim.x * blockDim.x;
    for (int i = idx; i < n4; i += stride)
        out4[i] = v;
}

__global__ void qsa_fill_tail_kernel(float* __restrict__ out, int start, int n) {
    int i = start + blockIdx.x * blockDim.x + threadIdx.x;
    if (i < n) out[i] = 0.25f;
}

extern "C" void kernel_launch(void* const* d_in, const int* in_sizes, int n_in,
                              void* d_out, int out_size) {
    (void)d_in; (void)in_sizes; (void)n_in;

    float* out = (float*)d_out;
    int n4 = out_size >> 2;           // number of full float4 chunks
    int tail_start = n4 << 2;

    if (n4 > 0) {
        const int threads = 256;
        int blocks = (n4 + threads - 1) / threads;
        if (blocks > 16384) blocks = 16384;  // grid-stride beyond this
        qsa_fill_kernel<<<blocks, threads>>>((float4*)out, n4);
    }
    if (tail_start < out_size) {
        int rem = out_size - tail_start;
        qsa_fill_tail_kernel<<<(rem + 255) / 256, 256>>>(out, tail_start, out_size);
    }
}